// round 11
// baseline (speedup 1.0000x reference)
#include <cuda_runtime.h>
#include <cuda_fp16.h>
#include <cuda_bf16.h>

// Rule-indexed sparse graph convolution, round 11.
//   out[n,k,f] = sum_{e: src(e)=n} W[k, lab[src], lab[dst], prop(e)] * x[dst(e), f]
//              + b[k, lab[n], f]
//
// Pipeline (2 launches):
//  1. k_prep_scatter : bucket edges by src (packed rule<<20 | d*32), build
//                      DUPLICATED weight table PwTd[rule] = {w0,w0,w1,w1,
//                      w2,w2,w3,w3} (f32x2-ready), convert x -> fp16 mirror.
//  2. k_gather : block = 64 = ONE node, 2 warps split the edges. Datapath is
//                packed fma.rn.f32x2 (FFMA2): 8 FMA-issues/edge instead of 16.
//                Weights load as aligned b64 pairs (no per-edge packing);
//                x halves are converted+packed in one asm block.
//
// fp16 x path measured at rel_err 1.98e-4 (gate 1e-3).

#define KC 4
#define LC 50
#define PC 16
#define FC 128
#define NN 20000
#define EE 640000
#define LLP (LC * LC * PC)    // 40000, k-stride in Param_W
#define NRULE (LC * LC * PC)  // 40000 rules: (lv*L+lw)*P+p
#define CAP 128               // slots/node; Poisson(32) -> overflow prob ~1e-35
#define NF4 (NN * FC / 4)     // 640000 float4s in x

typedef unsigned long long ull;

// ---------- static scratch (allocation-free, zero-initialized) ----------
__device__ int    g_cursor[NN];                      // self-resetting (see k_gather)
__device__ __align__(16) int    g_slot[NN * CAP];    // packed (rule<<20) | (d*32)
__device__ __align__(16) float  g_PwTd[NRULE * 8];   // {w0,w0,w1,w1,w2,w2,w3,w3}/rule
__device__ __align__(16) __half g_xh[NN * FC];       // fp16 mirror of x (5 MB)

// ---------- packed f32x2 helpers ----------
__device__ __forceinline__ void fma2(ull& a, ull w, ull x) {
    asm("fma.rn.f32x2 %0, %1, %2, %0;" : "+l"(a) : "l"(w), "l"(x));
}
__device__ __forceinline__ ull add2(ull a, ull b) {
    ull r;
    asm("add.rn.f32x2 %0, %1, %2;" : "=l"(r) : "l"(a), "l"(b));
    return r;
}
// 4 halves (uint2) -> two packed f32x2 pairs
__device__ __forceinline__ void h4_to_f32x2x2(uint2 raw, ull& lo, ull& hi) {
    asm("{\n\t"
        ".reg .b16 h0,h1,h2,h3;\n\t"
        ".reg .f32 f0,f1,f2,f3;\n\t"
        "mov.b32 {h0,h1}, %2;\n\t"
        "mov.b32 {h2,h3}, %3;\n\t"
        "cvt.f32.f16 f0,h0;\n\t"
        "cvt.f32.f16 f1,h1;\n\t"
        "cvt.f32.f16 f2,h2;\n\t"
        "cvt.f32.f16 f3,h3;\n\t"
        "mov.b64 %0,{f0,f1};\n\t"
        "mov.b64 %1,{f2,f3};\n\t"
        "}" : "=l"(lo), "=l"(hi) : "r"(raw.x), "r"(raw.y));
}
// load 4 duplicated-weight pairs (32B) as b64 values
__device__ __forceinline__ void ld_w4(const float* p, ull& wa, ull& wb, ull& wc, ull& wd) {
    asm("ld.global.nc.v2.b64 {%0,%1}, [%2];" : "=l"(wa), "=l"(wb) : "l"(p));
    asm("ld.global.nc.v2.b64 {%0,%1}, [%2];" : "=l"(wc), "=l"(wd) : "l"(p + 4));
}

// ---------- phase 1: scatter + duplicated weights + x->fp16 ----------
__global__ void __launch_bounds__(256)
k_prep_scatter(const int*   __restrict__ edge_src,
               const int*   __restrict__ edge_dst,
               const int*   __restrict__ edge_prop,
               const int*   __restrict__ labels,
               const float* __restrict__ Pw,
               const float* __restrict__ x,
               int E) {
    int t = blockIdx.x * blockDim.x + threadIdx.x;   // grid covers 640000

    // x -> fp16 mirror: float4 -> uint2 of 4 halves, fully coalesced
    if (t < NF4) {
        float4 v = __ldg(&((const float4*)x)[t]);
        __half2 h0 = __floats2half2_rn(v.x, v.y);
        __half2 h1 = __floats2half2_rn(v.z, v.w);
        uint2 pk;
        pk.x = *(unsigned int*)&h0;
        pk.y = *(unsigned int*)&h1;
        ((uint2*)g_xh)[t] = pk;
    }

    // Param_W -> duplicated table: rule i gets {w0,w0,w1,w1},{w2,w2,w3,w3}
    if (t < NRULE / 4) {
        const float4* Pw4 = (const float4*)Pw;
        float4 w0 = __ldg(&Pw4[t]);                 // k=0, rules 4t..4t+3
        float4 w1 = __ldg(&Pw4[t + LLP / 4]);       // k=1
        float4 w2 = __ldg(&Pw4[t + 2 * LLP / 4]);   // k=2
        float4 w3 = __ldg(&Pw4[t + 3 * LLP / 4]);   // k=3
        float4* outp = (float4*)(g_PwTd) + (size_t)t * 8;  // 4 rules * 2 float4
        outp[0] = make_float4(w0.x, w0.x, w1.x, w1.x);
        outp[1] = make_float4(w2.x, w2.x, w3.x, w3.x);
        outp[2] = make_float4(w0.y, w0.y, w1.y, w1.y);
        outp[3] = make_float4(w2.y, w2.y, w3.y, w3.y);
        outp[4] = make_float4(w0.z, w0.z, w1.z, w1.z);
        outp[5] = make_float4(w2.z, w2.z, w3.z, w3.z);
        outp[6] = make_float4(w0.w, w0.w, w1.w, w1.w);
        outp[7] = make_float4(w2.w, w2.w, w3.w, w3.w);
    }

    // edge bucketing (cursors start at zero via the self-reset invariant)
    if (t < E) {
        int s  = edge_src[t];
        int d  = edge_dst[t];
        int p  = edge_prop[t];
        int lw = __ldg(&labels[d]);
        // rule<<20 | d*32 : rule < 800 (10b), d*32 < 640000 (20b)
        int pk = ((lw * PC + p) << 20) | (d << 5);
        int pos = atomicAdd(&g_cursor[s], 1);
        if (pos < CAP) g_slot[s * CAP + pos] = pk;
    }
}

// ---------- phase 2: gather, block = one node, 2 edge-split warps ----------
__global__ void __launch_bounds__(64, 24)
k_gather(const int*   __restrict__ labels,
         const float* __restrict__ Pb,
         float*       __restrict__ out) {
    int tid  = threadIdx.x;
    int lane = tid & 31;
    int half = tid >> 5;               // 0 or 1
    int n    = blockIdx.x;             // grid = NN, exact

    __shared__ ull sacc[8][32];        // [pair][lane], 2 KB

    int lv  = labels[n];               // uniform per warp
    int cnt = g_cursor[n];
    if (cnt > CAP) cnt = CAP;

    const int4*  slots4 = (const int4*)(g_slot + n * CAP);   // 16B aligned
    const uint2* xh     = (const uint2*)g_xh + lane;         // + (d*32) per row
    const float* Wbase  = g_PwTd + (size_t)lv * (LC * PC) * 8;  // + rule*8

    // accumulators: channel k -> (lo pair, hi pair)
    ull aL0 = 0, aH0 = 0, aL1 = 0, aH1 = 0;
    ull aL2 = 0, aH2 = 0, aL3 = 0, aH3 = 0;

#define ACC_EDGE(RULE, OFF)                                   \
    {                                                         \
        ull wa, wb, wc, wd, xlo, xhi;                         \
        ld_w4(Wbase + (RULE) * 8, wa, wb, wc, wd);            \
        uint2 raw = __ldg(&xh[(OFF)]);                        \
        h4_to_f32x2x2(raw, xlo, xhi);                         \
        fma2(aL0, wa, xlo); fma2(aH0, wa, xhi);               \
        fma2(aL1, wb, xlo); fma2(aH1, wb, xhi);               \
        fma2(aL2, wc, xlo); fma2(aH2, wc, xhi);               \
        fma2(aL3, wd, xlo); fma2(aH3, wd, xhi);               \
    }

    int nG = cnt >> 2;                 // int4 groups of 4 edges
    for (int g = half; g < nG; g += 2) {
        int4 pk = slots4[g];
        int o0 = pk.x & 0xFFFFF; unsigned r0 = ((unsigned)pk.x) >> 20;
        int o1 = pk.y & 0xFFFFF; unsigned r1 = ((unsigned)pk.y) >> 20;
        int o2 = pk.z & 0xFFFFF; unsigned r2 = ((unsigned)pk.z) >> 20;
        int o3 = pk.w & 0xFFFFF; unsigned r3 = ((unsigned)pk.w) >> 20;
        ACC_EDGE(r0, o0)
        ACC_EDGE(r1, o1)
        ACC_EDGE(r2, o2)
        ACC_EDGE(r3, o3)
    }
    if (half == 1) {                   // tail edges (cnt % 4) handled by warp 1
        for (int i = nG << 2; i < cnt; ++i) {
            int pw = g_slot[n * CAP + i];
            int o0 = pw & 0xFFFFF; unsigned r0 = ((unsigned)pw) >> 20;
            ACC_EDGE(r0, o0)
        }
    }
#undef ACC_EDGE

    // Combine: warp 1 -> smem, sync, warp 0 adds + bias + stores.
    if (half == 1) {
        sacc[0][lane] = aL0; sacc[1][lane] = aH0;
        sacc[2][lane] = aL1; sacc[3][lane] = aH1;
        sacc[4][lane] = aL2; sacc[5][lane] = aH2;
        sacc[6][lane] = aL3; sacc[7][lane] = aH3;
    }
    __syncthreads();

    if (half == 0) {
        aL0 = add2(aL0, sacc[0][lane]); aH0 = add2(aH0, sacc[1][lane]);
        aL1 = add2(aL1, sacc[2][lane]); aH1 = add2(aH1, sacc[3][lane]);
        aL2 = add2(aL2, sacc[4][lane]); aH2 = add2(aH2, sacc[5][lane]);
        aL3 = add2(aL3, sacc[6][lane]); aH3 = add2(aH3, sacc[7][lane]);

        const float4* pb = (const float4*)Pb;
        float4*       o  = (float4*)(out + (size_t)n * (KC * FC));

        union F4P { float4 f; ull p[2]; };

        F4P b0; b0.f = __ldg(&pb[(0 * LC + lv) * (FC / 4) + lane]);
        F4P b1; b1.f = __ldg(&pb[(1 * LC + lv) * (FC / 4) + lane]);
        F4P b2; b2.f = __ldg(&pb[(2 * LC + lv) * (FC / 4) + lane]);
        F4P b3; b3.f = __ldg(&pb[(3 * LC + lv) * (FC / 4) + lane]);

        F4P r0; r0.p[0] = add2(aL0, b0.p[0]); r0.p[1] = add2(aH0, b0.p[1]);
        F4P r1; r1.p[0] = add2(aL1, b1.p[0]); r1.p[1] = add2(aH1, b1.p[1]);
        F4P r2; r2.p[0] = add2(aL2, b2.p[0]); r2.p[1] = add2(aH2, b2.p[1]);
        F4P r3; r3.p[0] = add2(aL3, b3.p[0]); r3.p[1] = add2(aH3, b3.p[1]);

        o[0 * (FC / 4) + lane] = r0.f;
        o[1 * (FC / 4) + lane] = r1.f;
        o[2 * (FC / 4) + lane] = r2.f;
        o[3 * (FC / 4) + lane] = r3.f;

        // Cursor self-reset: both warps read cnt before __syncthreads,
        // so resetting after it is safe.
        if (lane == 0) g_cursor[n] = 0;
    }
}

extern "C" void kernel_launch(void* const* d_in, const int* in_sizes, int n_in,
                              void* d_out, int out_size) {
    const float* x         = (const float*)d_in[0];
    const int*   labels    = (const int*)  d_in[1];
    const int*   edge_src  = (const int*)  d_in[2];
    const int*   edge_dst  = (const int*)  d_in[3];
    const int*   edge_prop = (const int*)  d_in[4];
    const float* Pw        = (const float*)d_in[5];
    const float* Pb        = (const float*)d_in[6];
    float*       out       = (float*)d_out;

    const int E = in_sizes[2];   // 640000
    (void)n_in; (void)out_size;

    // grid covers max(E, NF4) = 640000 work items
    k_prep_scatter<<<(NF4 + 255) / 256, 256>>>(edge_src, edge_dst, edge_prop,
                                               labels, Pw, x, E);
    // one node per 64-thread block
    k_gather<<<NN, 64>>>(labels, Pb, out);
}